// round 13
// baseline (speedup 1.0000x reference)
#include <cuda_runtime.h>
#include <cuda_bf16.h>
#include <cstdint>

#define DEV __device__ __forceinline__
typedef __nv_bfloat16 bf16;

DEV float qz4f(float x) {
    float f = rintf(x * 16.0f);
    f = fminf(fmaxf(f, -128.0f), 127.0f);
    return f * 0.0625f;
}
DEV float qz7f(float x) {
    float f = rintf(x * 128.0f);
    f = fminf(fmaxf(f, -128.0f), 127.0f);
    return f * 0.0078125f;
}
// quantize to raw int in [-128,127]
DEV int qi4(float x) {
    float f = rintf(x * 16.0f);
    return (int)fminf(fmaxf(f, -128.0f), 127.0f);
}
DEV int qi7(float x) {
    float f = rintf(x * 128.0f);
    return (int)fminf(fmaxf(f, -128.0f), 127.0f);
}
DEV uint32_t pack2(float x, float y) {
    __nv_bfloat162 t;
    t.x = __float2bfloat16(x); t.y = __float2bfloat16(y);
    return *reinterpret_cast<uint32_t*>(&t);
}
DEV void unpack2(uint32_t u, float& x, float& y) {
    __nv_bfloat162 t = *reinterpret_cast<__nv_bfloat162*>(&u);
    x = __bfloat162float(t.x); y = __bfloat162float(t.y);
}
DEV uint32_t packs8(int a, int b, int c, int d) {
    return (uint32_t)(a & 255) | ((uint32_t)(b & 255) << 8) |
           ((uint32_t)(c & 255) << 16) | ((uint32_t)(d & 255) << 24);
}

// ---------------------------------------------------------------------------
// Scratch.  int8 activations/weights for s8 GEMMs; bf16 attention operands.
// ---------------------------------------------------------------------------
__device__ int8_t g_hq  [4096L * 1024];   // affine out, qz4 ints
__device__ bf16   g_qq  [4096L * 1024];   // qz4 vals (bf16, attention input)
__device__ bf16   g_kvq [4096L * 2048];
__device__ int8_t g_zq  [4096L * 1024];   // attn context, qz4 ints
__device__ bf16   g_pj  [4096L * 1024];
__device__ bf16   g_x1  [4096L * 1024];
__device__ int8_t g_mid [4096L * 4096];   // fc1 out, qz4 ints
__device__ bf16   g_f2  [4096L * 1024];
__device__ int8_t g_wq  [1024L * 1024];   // weights, qz7 ints
__device__ int8_t g_wkv [2048L * 1024];
__device__ int8_t g_wpj [1024L * 1024];
__device__ int8_t g_wf1 [4096L * 1024];
__device__ int8_t g_wf2 [1024L * 4096];

// ---------------------------------------------------------------------------
// PTX wrappers
// ---------------------------------------------------------------------------
DEV void ldsm_x4(uint32_t& r0, uint32_t& r1, uint32_t& r2, uint32_t& r3, uint32_t addr) {
    asm volatile("ldmatrix.sync.aligned.m8n8.x4.shared.b16 {%0,%1,%2,%3}, [%4];\n"
                 : "=r"(r0), "=r"(r1), "=r"(r2), "=r"(r3) : "r"(addr));
}
DEV void ldsm_x4_t(uint32_t& r0, uint32_t& r1, uint32_t& r2, uint32_t& r3, uint32_t addr) {
    asm volatile("ldmatrix.sync.aligned.m8n8.x4.trans.shared.b16 {%0,%1,%2,%3}, [%4];\n"
                 : "=r"(r0), "=r"(r1), "=r"(r2), "=r"(r3) : "r"(addr));
}
DEV void mma16816(float* c, const uint32_t* a, const uint32_t* b) {
    asm volatile(
        "mma.sync.aligned.m16n8k16.row.col.f32.bf16.bf16.f32 "
        "{%0,%1,%2,%3}, {%4,%5,%6,%7}, {%8,%9}, {%0,%1,%2,%3};\n"
        : "+f"(c[0]), "+f"(c[1]), "+f"(c[2]), "+f"(c[3])
        : "r"(a[0]), "r"(a[1]), "r"(a[2]), "r"(a[3]), "r"(b[0]), "r"(b[1]));
}
// int8 tensor-core MMA, K=32, s32 accumulate (exact)
DEV void mma16832s8(int32_t* c, const uint32_t* a, const uint32_t* b) {
    asm volatile(
        "mma.sync.aligned.m16n8k32.row.col.s32.s8.s8.s32 "
        "{%0,%1,%2,%3}, {%4,%5,%6,%7}, {%8,%9}, {%0,%1,%2,%3};\n"
        : "+r"(c[0]), "+r"(c[1]), "+r"(c[2]), "+r"(c[3])
        : "r"(a[0]), "r"(a[1]), "r"(a[2]), "r"(a[3]), "r"(b[0]), "r"(b[1]));
}
DEV uint32_t sw128(uint32_t byte) { return byte ^ ((byte >> 3) & 0x70); }
DEV uint32_t sw64(uint32_t byte)  { return byte ^ ((byte >> 3) & 0x30); }

DEV void cpasync16(uint32_t dst, const void* src) {
    asm volatile("cp.async.cg.shared.global [%0], [%1], 16;\n" :: "r"(dst), "l"(src));
}
DEV void cpcommit() { asm volatile("cp.async.commit_group;\n" ::: "memory"); }
template <int N> DEV void cpwait() { asm volatile("cp.async.wait_group %0;\n" :: "n"(N) : "memory"); }

// ---------------------------------------------------------------------------
// s8 weight GEMM:  acc[m,n] = sum_k Ai8[m,k]*Bi8[n,k]  (s32, exact)
//   y = acc/2048 (+qz7 bias) (relu); out bf16(qz4) or int8(qz4 ints)
// BM=BN=128, BK=64 int8 (64B rows, SW64), 4 cp.async stages, 1 barrier/iter.
// EPI: 0 none; 2 +bias; 3 relu(+bias).   OUTI8: 0 bf16 out, 1 int8 out.
// ---------------------------------------------------------------------------
template <int EPI, int OUTI8>
__global__ void __launch_bounds__(256)
gemm_s8(const int8_t* __restrict__ A, const int8_t* __restrict__ B,
        const float* __restrict__ bias, void* __restrict__ Cv, int N, int K)
{
    extern __shared__ char smem_raw[];
    const int tid = threadIdx.x, warp = tid >> 5, lane = tid & 31;
    const int wm = (warp >> 1) * 32, wn = (warp & 1) * 64;
    const long long m0 = (long long)blockIdx.y * 128;
    const long long n0 = (long long)blockIdx.x * 128;
    const uint32_t sbase = (uint32_t)__cvta_generic_to_shared(smem_raw);

    const int8_t* Ap = A + m0 * K;
    const int8_t* Bp = B + n0 * K;

    int32_t acc[2][8][4];
#pragma unroll
    for (int i = 0; i < 2; i++)
#pragma unroll
        for (int j = 0; j < 8; j++)
#pragma unroll
            for (int p = 0; p < 4; p++) acc[i][j][p] = 0;

    // stage s at sbase + s*16384: A [128][64] int8 at +0, B at +8192
    auto loadtile = [&](int kt) {
        const int s = kt & 3;
        const uint32_t sa = sbase + s * 16384;
        const uint32_t sb = sa + 8192;
        const int8_t* Ak = Ap + (long long)kt * 64;
        const int8_t* Bk = Bp + (long long)kt * 64;
#pragma unroll
        for (int v = 0; v < 2; v++) {
            int idx = tid + v * 256;
            int r = idx >> 2, c = idx & 3;
            uint32_t off = sw64(r * 64 + c * 16);
            cpasync16(sa + off, Ak + (long long)r * K + c * 16);
            cpasync16(sb + off, Bk + (long long)r * K + c * 16);
        }
    };

    const int nt = K >> 6;

#pragma unroll
    for (int p = 0; p < 3; p++) {
        if (p < nt) loadtile(p);
        cpcommit();
    }

    for (int t = 0; t < nt; t++) {
        cpwait<2>();
        __syncthreads();
        if (t + 3 < nt) loadtile(t + 3);
        cpcommit();

        const uint32_t sa = sbase + (t & 3) * 16384;
        const uint32_t sb = sa + 8192;
#pragma unroll
        for (int ks = 0; ks < 2; ks++) {       // each ks covers k32
            uint32_t a[2][4];
#pragma unroll
            for (int mf = 0; mf < 2; mf++) {
                int r = wm + mf * 16 + (lane & 15);
                ldsm_x4(a[mf][0], a[mf][1], a[mf][2], a[mf][3],
                        sa + sw64(r * 64 + ks * 32 + (lane >> 4) * 16));
            }
            uint32_t bfr[8][2];
#pragma unroll
            for (int np = 0; np < 4; np++) {
                uint32_t r0, r1, r2, r3;
                int n = wn + np * 16 + (lane >> 4) * 8 + (lane & 7);
                ldsm_x4(r0, r1, r2, r3,
                        sb + sw64(n * 64 + ks * 32 + ((lane >> 3) & 1) * 16));
                bfr[np * 2][0] = r0; bfr[np * 2][1] = r1;
                bfr[np * 2 + 1][0] = r2; bfr[np * 2 + 1][1] = r3;
            }
#pragma unroll
            for (int mf = 0; mf < 2; mf++)
#pragma unroll
                for (int nf = 0; nf < 8; nf++)
                    mma16832s8(acc[mf][nf], a[mf], bfr[nf]);
        }
    }

    const float sc = 1.0f / 2048.0f;   // qz4(1/16) * qz7(1/128)
    const int g = lane >> 2, tg = lane & 3;
#pragma unroll
    for (int mf = 0; mf < 2; mf++) {
        long long r0 = m0 + wm + mf * 16 + g;
#pragma unroll
        for (int nf = 0; nf < 8; nf++) {
            long long cc = n0 + wn + nf * 8 + 2 * tg;
            float y0 = (float)acc[mf][nf][0] * sc;
            float y1 = (float)acc[mf][nf][1] * sc;
            float y2 = (float)acc[mf][nf][2] * sc;
            float y3 = (float)acc[mf][nf][3] * sc;
            if (EPI == 2 || EPI == 3) {
                float qb0 = qz7f(__ldg(bias + cc)), qb1 = qz7f(__ldg(bias + cc + 1));
                y0 += qb0; y1 += qb1; y2 += qb0; y3 += qb1;
            }
            if (EPI == 3) {
                y0 = fmaxf(y0, 0.0f); y1 = fmaxf(y1, 0.0f);
                y2 = fmaxf(y2, 0.0f); y3 = fmaxf(y3, 0.0f);
            }
            if (OUTI8) {
                int8_t* C = (int8_t*)Cv;
                int i0 = qi4(y0), i1 = qi4(y1), i2 = qi4(y2), i3 = qi4(y3);
                *(uint16_t*)(C + r0 * N + cc) =
                    (uint16_t)((i0 & 255) | ((i1 & 255) << 8));
                *(uint16_t*)(C + (r0 + 8) * N + cc) =
                    (uint16_t)((i2 & 255) | ((i3 & 255) << 8));
            } else {
                bf16* C = (bf16*)Cv;
                *(uint32_t*)(C + r0 * N + cc) = pack2(qz4f(y0), qz4f(y1));
                *(uint32_t*)(C + (r0 + 8) * N + cc) = pack2(qz4f(y2), qz4f(y3));
            }
        }
    }
}

// ---------------------------------------------------------------------------
// Fused attention (bf16 mma path, int8 zq epilogue)
// ---------------------------------------------------------------------------
__global__ void __launch_bounds__(256)
attn_fused(const bf16* __restrict__ qq, const bf16* __restrict__ kvq,
           int8_t* __restrict__ zq)
{
    __shared__ __align__(128) char smem_raw[49152];
    const int tid = threadIdx.x, warp = tid >> 5, lane = tid & 31;
    const int bh = blockIdx.y;
    const int b = bh >> 4, h = bh & 15;
    const long long qrow0 = (long long)b * 1024 + (long long)blockIdx.x * 128;

    const bf16* Qp = qq + qrow0 * 1024 + h * 64;
    const bf16* Kp = kvq + (long long)b * 1024 * 2048 + h * 64;
    const bf16* Vp = Kp + 1024;

    const uint32_t sbase = (uint32_t)__cvta_generic_to_shared(smem_raw);
    const uint32_t sQ = sbase;
    const uint32_t sS = sbase + 16384;
    const int wm = warp * 16;

#pragma unroll
    for (int v = 0; v < 4; v++) {
        int idx = tid + v * 256;
        int r = idx >> 3, c = idx & 7;
        cpasync16(sQ + sw128(r * 128 + c * 16), Qp + (long long)r * 1024 + c * 8);
    }

    auto loadK128 = [&](int s, int c) {
        uint32_t basea = sS + s * 16384;
#pragma unroll
        for (int v = 0; v < 4; v++) {
            int idx = tid + v * 256;
            int r = idx >> 3, cd = idx & 7;
            cpasync16(basea + sw128(r * 128 + cd * 16),
                      Kp + (long long)(c * 128 + r) * 2048 + cd * 8);
        }
    };

    loadK128(0, 0); cpcommit();

    float m[2] = {-1e30f, -1e30f}, l[2] = {0.0f, 0.0f};

    for (int c = 0; c < 8; c++) {
        if (c + 1 < 8) { loadK128((c + 1) & 1, c + 1); cpcommit(); cpwait<1>(); }
        else           { cpwait<0>(); }
        __syncthreads();
        uint32_t sk = sS + (c & 1) * 16384;

        float acc[16][4];
#pragma unroll
        for (int i = 0; i < 16; i++)
#pragma unroll
            for (int p = 0; p < 4; p++) acc[i][p] = 0.0f;

#pragma unroll
        for (int ks = 0; ks < 4; ks++) {
            uint32_t a[4];
            int ar = wm + (lane & 15);
            ldsm_x4(a[0], a[1], a[2], a[3],
                    sQ + sw128(ar * 128 + ks * 32 + (lane >> 4) * 16));
            uint32_t bfr[16][2];
#pragma unroll
            for (int np = 0; np < 8; np++) {
                uint32_t r0, r1, r2, r3;
                int n = np * 16 + (lane >> 4) * 8 + (lane & 7);
                ldsm_x4(r0, r1, r2, r3,
                        sk + sw128(n * 128 + ks * 32 + ((lane >> 3) & 1) * 16));
                bfr[np * 2][0] = r0; bfr[np * 2][1] = r1;
                bfr[np * 2 + 1][0] = r2; bfr[np * 2 + 1][1] = r3;
            }
#pragma unroll
            for (int nf = 0; nf < 16; nf++)
                mma16816(acc[nf], a, bfr[nf]);
        }

        float mx0 = -1e30f, mx1 = -1e30f;
#pragma unroll
        for (int nf = 0; nf < 16; nf++) {
            acc[nf][0] = qz4f(acc[nf][0] * 0.125f);
            acc[nf][1] = qz4f(acc[nf][1] * 0.125f);
            acc[nf][2] = qz4f(acc[nf][2] * 0.125f);
            acc[nf][3] = qz4f(acc[nf][3] * 0.125f);
            mx0 = fmaxf(mx0, fmaxf(acc[nf][0], acc[nf][1]));
            mx1 = fmaxf(mx1, fmaxf(acc[nf][2], acc[nf][3]));
        }
        mx0 = fmaxf(mx0, __shfl_xor_sync(0xffffffffu, mx0, 1));
        mx0 = fmaxf(mx0, __shfl_xor_sync(0xffffffffu, mx0, 2));
        mx1 = fmaxf(mx1, __shfl_xor_sync(0xffffffffu, mx1, 1));
        mx1 = fmaxf(mx1, __shfl_xor_sync(0xffffffffu, mx1, 2));

        float mn0 = fmaxf(m[0], mx0), mn1 = fmaxf(m[1], mx1);
        float s0 = 0.0f, s1 = 0.0f;
#pragma unroll
        for (int nf = 0; nf < 16; nf++) {
            s0 += expf(acc[nf][0] - mn0) + expf(acc[nf][1] - mn0);
            s1 += expf(acc[nf][2] - mn1) + expf(acc[nf][3] - mn1);
        }
        s0 += __shfl_xor_sync(0xffffffffu, s0, 1);
        s0 += __shfl_xor_sync(0xffffffffu, s0, 2);
        s1 += __shfl_xor_sync(0xffffffffu, s1, 1);
        s1 += __shfl_xor_sync(0xffffffffu, s1, 2);

        l[0] = l[0] * expf(m[0] - mn0) + s0; m[0] = mn0;
        l[1] = l[1] * expf(m[1] - mn1) + s1; m[1] = mn1;
        __syncthreads();
    }

    const float linv0 = 1.0f / l[0], linv1 = 1.0f / l[1];

    auto loadKV64 = [&](int s, int c) {
        uint32_t basea = sS + s * 16384;
#pragma unroll
        for (int v = 0; v < 2; v++) {
            int idx = tid + v * 256;
            int r = idx >> 3, cd = idx & 7;
            uint32_t off = sw128(r * 128 + cd * 16);
            cpasync16(basea + off, Kp + (long long)(c * 64 + r) * 2048 + cd * 8);
            cpasync16(basea + 8192 + off, Vp + (long long)(c * 64 + r) * 2048 + cd * 8);
        }
    };

    float zacc[8][4];
#pragma unroll
    for (int j = 0; j < 8; j++)
#pragma unroll
        for (int p = 0; p < 4; p++) zacc[j][p] = 0.0f;

    loadKV64(0, 0); cpcommit();

    for (int c = 0; c < 16; c++) {
        if (c + 1 < 16) { loadKV64((c + 1) & 1, c + 1); cpcommit(); cpwait<1>(); }
        else            { cpwait<0>(); }
        __syncthreads();
        uint32_t sk = sS + (c & 1) * 16384;
        uint32_t sv = sk + 8192;

        float acc[8][4];
#pragma unroll
        for (int i = 0; i < 8; i++)
#pragma unroll
            for (int p = 0; p < 4; p++) acc[i][p] = 0.0f;

#pragma unroll
        for (int ks = 0; ks < 4; ks++) {
            uint32_t a[4];
            int ar = wm + (lane & 15);
            ldsm_x4(a[0], a[1], a[2], a[3],
                    sQ + sw128(ar * 128 + ks * 32 + (lane >> 4) * 16));
            uint32_t bfr[8][2];
#pragma unroll
            for (int np = 0; np < 4; np++) {
                uint32_t r0, r1, r2, r3;
                int n = np * 16 + (lane >> 4) * 8 + (lane & 7);
                ldsm_x4(r0, r1, r2, r3,
                        sk + sw128(n * 128 + ks * 32 + ((lane >> 3) & 1) * 16));
                bfr[np * 2][0] = r0; bfr[np * 2][1] = r1;
                bfr[np * 2 + 1][0] = r2; bfr[np * 2 + 1][1] = r3;
            }
#pragma unroll
            for (int nf = 0; nf < 8; nf++)
                mma16816(acc[nf], a, bfr[nf]);
        }

        uint32_t afr[4][4];
#pragma unroll
        for (int kk = 0; kk < 4; kk++) {
            float p00 = qz7f(expf(qz4f(acc[2 * kk][0] * 0.125f) - m[0]) * linv0);
            float p01 = qz7f(expf(qz4f(acc[2 * kk][1] * 0.125f) - m[0]) * linv0);
            float p02 = qz7f(expf(qz4f(acc[2 * kk][2] * 0.125f) - m[1]) * linv1);
            float p03 = qz7f(expf(qz4f(acc[2 * kk][3] * 0.125f) - m[1]) * linv1);
            float p10 = qz7f(expf(qz4f(acc[2 * kk + 1][0] * 0.125f) - m[0]) * linv0);
            float p11 = qz7f(expf(qz4f(acc[2 * kk + 1][1] * 0.125f) - m[0]) * linv0);
            float p12 = qz7f(expf(qz4f(acc[2 * kk + 1][2] * 0.125f) - m[1]) * linv1);
            float p13 = qz7f(expf(qz4f(acc[2 * kk + 1][3] * 0.125f) - m[1]) * linv1);
            afr[kk][0] = pack2(p00, p01);
            afr[kk][1] = pack2(p02, p03);
            afr[kk][2] = pack2(p10, p11);
            afr[kk][3] = pack2(p12, p13);
        }

#pragma unroll
        for (int kk = 0; kk < 4; kk++) {
            uint32_t vfr[8][2];
#pragma unroll
            for (int np = 0; np < 4; np++) {
                uint32_t r0, r1, r2, r3;
                int r = kk * 16 + (lane & 15);
                int n = np * 16 + (lane >> 4) * 8;
                ldsm_x4_t(r0, r1, r2, r3, sv + sw128(r * 128 + n * 2));
                vfr[np * 2][0] = r0; vfr[np * 2][1] = r1;
                vfr[np * 2 + 1][0] = r2; vfr[np * 2 + 1][1] = r3;
            }
#pragma unroll
            for (int nf = 0; nf < 8; nf++)
                mma16816(zacc[nf], afr[kk], vfr[nf]);
        }
        __syncthreads();
    }

    // epilogue: zq = qz4 ints (int8)
    const int g = lane >> 2, tg = lane & 3;
    const long long r0 = qrow0 + wm + g;
#pragma unroll
    for (int nf = 0; nf < 8; nf++) {
        long long cc = (long long)h * 64 + nf * 8 + 2 * tg;
        int i0 = qi4(zacc[nf][0]), i1 = qi4(zacc[nf][1]);
        int i2 = qi4(zacc[nf][2]), i3 = qi4(zacc[nf][3]);
        *(uint16_t*)(zq + r0 * 1024 + cc) = (uint16_t)((i0 & 255) | ((i1 & 255) << 8));
        *(uint16_t*)(zq + (r0 + 8) * 1024 + cc) = (uint16_t)((i2 & 255) | ((i3 & 255) << 8));
    }
}

// ---------------------------------------------------------------------------
// Elementwise kernels
// ---------------------------------------------------------------------------
__global__ void __launch_bounds__(256) quantw_kernel(
    const float* __restrict__ W, int8_t* __restrict__ O)
{
    long long i = (long long)blockIdx.x * 256 + threadIdx.x;
    float4 v = reinterpret_cast<const float4*>(W)[i];
    reinterpret_cast<uint32_t*>(O)[i] = packs8(qi7(v.x), qi7(v.y), qi7(v.z), qi7(v.w));
}

__global__ void __launch_bounds__(256) affine_f32_kernel(
    const float* __restrict__ X, const float* __restrict__ w,
    const float* __restrict__ b, int8_t* __restrict__ O)
{
    long long i = (long long)blockIdx.x * 256 + threadIdx.x;
    const float qw = qz4f(w[0]);
    const float qb = qz4f(b[0]);
    float4 v = reinterpret_cast<const float4*>(X)[i];
    int i0 = qi4(qz4f(qz4f(v.x) * qw) + qb);
    int i1 = qi4(qz4f(qz4f(v.y) * qw) + qb);
    int i2 = qi4(qz4f(qz4f(v.z) * qw) + qb);
    int i3 = qi4(qz4f(qz4f(v.w) * qw) + qb);
    reinterpret_cast<uint32_t*>(O)[i] = packs8(i0, i1, i2, i3);
}

__global__ void __launch_bounds__(256) affine_bf16_kernel(
    const bf16* __restrict__ X, const float* __restrict__ w,
    const float* __restrict__ b, int8_t* __restrict__ O)
{
    long long i = (long long)blockIdx.x * 256 + threadIdx.x;
    const float qw = qz4f(w[0]);
    const float qb = qz4f(b[0]);
    uint2 u = reinterpret_cast<const uint2*>(X)[i];
    float v0, v1, v2, v3;
    unpack2(u.x, v0, v1); unpack2(u.y, v2, v3);
    int i0 = qi4(qz4f(qz4f(v0) * qw) + qb);
    int i1 = qi4(qz4f(qz4f(v1) * qw) + qb);
    int i2 = qi4(qz4f(qz4f(v2) * qw) + qb);
    int i3 = qi4(qz4f(qz4f(v3) * qw) + qb);
    reinterpret_cast<uint32_t*>(O)[i] = packs8(i0, i1, i2, i3);
}

__global__ void __launch_bounds__(256) add1_kernel(
    const float* __restrict__ X, const bf16* __restrict__ P, bf16* __restrict__ O)
{
    long long i = (long long)blockIdx.x * 256 + threadIdx.x;
    float4 x = reinterpret_cast<const float4*>(X)[i];
    uint2 p = reinterpret_cast<const uint2*>(P)[i];
    float p0, p1, p2, p3;
    unpack2(p.x, p0, p1); unpack2(p.y, p2, p3);
    uint2 o;
    o.x = pack2(qz4f(x.x) + p0, qz4f(x.y) + p1);
    o.y = pack2(qz4f(x.z) + p2, qz4f(x.w) + p3);
    reinterpret_cast<uint2*>(O)[i] = o;
}

__global__ void __launch_bounds__(256) add2_kernel(
    const bf16* __restrict__ X1, const bf16* __restrict__ F, float* __restrict__ O)
{
    long long i = (long long)blockIdx.x * 256 + threadIdx.x;
    uint2 a = reinterpret_cast<const uint2*>(X1)[i];
    uint2 f = reinterpret_cast<const uint2*>(F)[i];
    float a0, a1, a2, a3, f0, f1, f2v, f3;
    unpack2(a.x, a0, a1); unpack2(a.y, a2, a3);
    unpack2(f.x, f0, f1); unpack2(f.y, f2v, f3);
    float4 o;
    o.x = qz4f(a0) + f0; o.y = qz4f(a1) + f1;
    o.z = qz4f(a2) + f2v; o.w = qz4f(a3) + f3;
    reinterpret_cast<float4*>(O)[i] = o;
}

// ---------------------------------------------------------------------------
// Launcher
// ---------------------------------------------------------------------------
#define GEMM_SMEM 65536

extern "C" void kernel_launch(void* const* d_in, const int* in_sizes, int n_in,
                              void* d_out, int out_size)
{
    const float* x      = (const float*)d_in[0];
    const float* q_w    = (const float*)d_in[1];
    const float* kv_w   = (const float*)d_in[2];
    const float* proj_w = (const float*)d_in[3];
    const float* proj_b = (const float*)d_in[4];
    const float* fc1_w  = (const float*)d_in[5];
    const float* fc1_b  = (const float*)d_in[6];
    const float* fc2_w  = (const float*)d_in[7];
    const float* fc2_b  = (const float*)d_in[8];
    const float* aff1_w = (const float*)d_in[9];
    const float* aff1_b = (const float*)d_in[10];
    const float* aff2_w = (const float*)d_in[11];
    const float* aff2_b = (const float*)d_in[12];
    float* out = (float*)d_out;

    int8_t *hq, *zq, *mid, *wq, *wkv, *wpj, *wf1, *wf2;
    bf16 *qq, *kvq, *pj, *x1, *f2;
    cudaGetSymbolAddress((void**)&hq,  g_hq);
    cudaGetSymbolAddress((void**)&qq,  g_qq);
    cudaGetSymbolAddress((void**)&kvq, g_kvq);
    cudaGetSymbolAddress((void**)&zq,  g_zq);
    cudaGetSymbolAddress((void**)&pj,  g_pj);
    cudaGetSymbolAddress((void**)&x1,  g_x1);
    cudaGetSymbolAddress((void**)&mid, g_mid);
    cudaGetSymbolAddress((void**)&f2,  g_f2);
    cudaGetSymbolAddress((void**)&wq,  g_wq);
    cudaGetSymbolAddress((void**)&wkv, g_wkv);
    cudaGetSymbolAddress((void**)&wpj, g_wpj);
    cudaGetSymbolAddress((void**)&wf1, g_wf1);
    cudaGetSymbolAddress((void**)&wf2, g_wf2);

    static bool attr_done = false;
    if (!attr_done) {
        cudaFuncSetAttribute(gemm_s8<0, 0>, cudaFuncAttributeMaxDynamicSharedMemorySize, GEMM_SMEM);
        cudaFuncSetAttribute(gemm_s8<2, 0>, cudaFuncAttributeMaxDynamicSharedMemorySize, GEMM_SMEM);
        cudaFuncSetAttribute(gemm_s8<3, 1>, cudaFuncAttributeMaxDynamicSharedMemorySize, GEMM_SMEM);
        attr_done = true;
    }

    // 0: hq = qz4 ints of affine(x, aff1)
    affine_f32_kernel<<<4096, 256>>>(x, aff1_w, aff1_b, hq);
    // 1-2: quantize q/kv weights -> int8
    quantw_kernel<<<1024, 256>>>(q_w, wq);
    quantw_kernel<<<2048, 256>>>(kv_w, wkv);
    // 3: qq = qz4(hq @ wq^T)  [s8 GEMM, bf16 out]
    gemm_s8<0, 0><<<dim3(8, 32), 256, GEMM_SMEM>>>(hq, wq, nullptr, qq, 1024, 1024);
    // 4: kvq = qz4(hq @ wkv^T)
    gemm_s8<0, 0><<<dim3(16, 32), 256, GEMM_SMEM>>>(hq, wkv, nullptr, kvq, 2048, 1024);
    // 5: fused attention (bf16 in, int8 zq out)
    attn_fused<<<dim3(8, 64), 256>>>(qq, kvq, zq);
    // 6: proj weights
    quantw_kernel<<<1024, 256>>>(proj_w, wpj);
    // 7: pj = qz4(zq @ wpj^T + qz7(proj_b))  [bf16 out]
    gemm_s8<2, 0><<<dim3(8, 32), 256, GEMM_SMEM>>>(zq, wpj, proj_b, pj, 1024, 1024);
    // 8: x1 = qz4(x) + pj
    add1_kernel<<<4096, 256>>>(x, pj, x1);
    // 9: hq = qz4 ints of affine(x1, aff2)
    affine_bf16_kernel<<<4096, 256>>>(x1, aff2_w, aff2_b, hq);
    // 10-11: fc1 [relu, int8 out]
    quantw_kernel<<<4096, 256>>>(fc1_w, wf1);
    gemm_s8<3, 1><<<dim3(32, 32), 256, GEMM_SMEM>>>(hq, wf1, fc1_b, mid, 4096, 1024);
    // 12-13: fc2 [bf16 out]
    quantw_kernel<<<4096, 256>>>(fc2_w, wf2);
    gemm_s8<2, 0><<<dim3(8, 32), 256, GEMM_SMEM>>>(mid, wf2, fc2_b, f2, 1024, 4096);
    // 14: out = qz4(x1) + f2
    add2_kernel<<<4096, 256>>>(x1, f2, out);
}

// round 15
// speedup vs baseline: 1.9348x; 1.9348x over previous
#include <cuda_runtime.h>
#include <cuda_bf16.h>
#include <cstdint>

#define DEV __device__ __forceinline__
typedef __nv_bfloat16 bf16;

DEV float qz4f(float x) {
    float f = rintf(x * 16.0f);
    f = fminf(fmaxf(f, -128.0f), 127.0f);
    return f * 0.0625f;
}
DEV float qz7f(float x) {
    float f = rintf(x * 128.0f);
    f = fminf(fmaxf(f, -128.0f), 127.0f);
    return f * 0.0078125f;
}
DEV uint32_t pack2(float x, float y) {
    __nv_bfloat162 t;
    t.x = __float2bfloat16(x); t.y = __float2bfloat16(y);
    return *reinterpret_cast<uint32_t*>(&t);
}
DEV void unpack2(uint32_t u, float& x, float& y) {
    __nv_bfloat162 t = *reinterpret_cast<__nv_bfloat162*>(&u);
    x = __bfloat162float(t.x); y = __bfloat162float(t.y);
}

// ---------------------------------------------------------------------------
// Scratch
// ---------------------------------------------------------------------------
__device__ bf16 g_hq   [4096L * 1024];
__device__ bf16 g_qkv  [4096L * 3072];   // combined q|k|v, row stride 3072
__device__ bf16 g_zq   [4096L * 1024];
__device__ bf16 g_pj   [4096L * 1024];
__device__ bf16 g_x1   [4096L * 1024];
__device__ bf16 g_mid  [4096L * 4096];
__device__ bf16 g_f2   [4096L * 1024];
__device__ bf16 g_wqkv [3072L * 1024];   // combined q_w|kv_w, qz7
__device__ bf16 g_wpj  [1024L * 1024];
__device__ bf16 g_wf1  [4096L * 1024];
__device__ bf16 g_wf2  [1024L * 4096];

// ---------------------------------------------------------------------------
// PTX wrappers
// ---------------------------------------------------------------------------
DEV void ldsm_x4(uint32_t& r0, uint32_t& r1, uint32_t& r2, uint32_t& r3, uint32_t addr) {
    asm volatile("ldmatrix.sync.aligned.m8n8.x4.shared.b16 {%0,%1,%2,%3}, [%4];\n"
                 : "=r"(r0), "=r"(r1), "=r"(r2), "=r"(r3) : "r"(addr));
}
DEV void ldsm_x4_t(uint32_t& r0, uint32_t& r1, uint32_t& r2, uint32_t& r3, uint32_t addr) {
    asm volatile("ldmatrix.sync.aligned.m8n8.x4.trans.shared.b16 {%0,%1,%2,%3}, [%4];\n"
                 : "=r"(r0), "=r"(r1), "=r"(r2), "=r"(r3) : "r"(addr));
}
DEV void mma16816(float* c, const uint32_t* a, const uint32_t* b) {
    asm volatile(
        "mma.sync.aligned.m16n8k16.row.col.f32.bf16.bf16.f32 "
        "{%0,%1,%2,%3}, {%4,%5,%6,%7}, {%8,%9}, {%0,%1,%2,%3};\n"
        : "+f"(c[0]), "+f"(c[1]), "+f"(c[2]), "+f"(c[3])
        : "r"(a[0]), "r"(a[1]), "r"(a[2]), "r"(a[3]), "r"(b[0]), "r"(b[1]));
}
DEV uint32_t sw128(uint32_t byte) { return byte ^ ((byte >> 3) & 0x70); }

DEV void cpasync16(uint32_t dst, const void* src) {
    asm volatile("cp.async.cg.shared.global [%0], [%1], 16;\n" :: "r"(dst), "l"(src));
}
DEV void cpcommit() { asm volatile("cp.async.commit_group;\n" ::: "memory"); }
template <int N> DEV void cpwait() { asm volatile("cp.async.wait_group %0;\n" :: "n"(N) : "memory"); }

// ---------------------------------------------------------------------------
// Pipelined weight GEMM (round-3 engine, measured 264 TF/s = mma.sync ceiling)
// C[m,n] = epi( sum_k A[m,k]*B[n,k] ); BM=BN=128, BK=64, 2 stages.
// EPI: 0 qz4; 2 qz4(+qz7 bias); 3 qz4(relu(+qz7 bias)). smem 64KB dynamic.
// ---------------------------------------------------------------------------
template <int EPI>
__global__ void __launch_bounds__(256)
gemm_pipe(const bf16* __restrict__ A, const bf16* __restrict__ B,
          const float* __restrict__ bias, bf16* __restrict__ C, int N, int K)
{
    extern __shared__ char smem_raw[];
    const int tid = threadIdx.x, warp = tid >> 5, lane = tid & 31;
    const int wm = (warp >> 1) * 32, wn = (warp & 1) * 64;
    const long long m0 = (long long)blockIdx.y * 128;
    const long long n0 = (long long)blockIdx.x * 128;
    const uint32_t sbase = (uint32_t)__cvta_generic_to_shared(smem_raw);

    const bf16* Ap = A + m0 * K;
    const bf16* Bp = B + n0 * K;

    float acc[2][8][4];
#pragma unroll
    for (int i = 0; i < 2; i++)
#pragma unroll
        for (int j = 0; j < 8; j++)
#pragma unroll
            for (int p = 0; p < 4; p++) acc[i][j][p] = 0.0f;

    auto loadtile = [&](int s, int kt) {
        uint32_t sa = sbase + s * 32768;
        uint32_t sb = sa + 16384;
        const bf16* Ak = Ap + (long long)kt * 64;
        const bf16* Bk = Bp + (long long)kt * 64;
#pragma unroll
        for (int v = 0; v < 4; v++) {
            int idx = tid + v * 256;
            int r = idx >> 3, c = idx & 7;
            uint32_t off = sw128(r * 128 + c * 16);
            cpasync16(sa + off, Ak + (long long)r * K + c * 8);
            cpasync16(sb + off, Bk + (long long)r * K + c * 8);
        }
    };

    const int nt = K >> 6;
    loadtile(0, 0); cpcommit();

    for (int t = 0; t < nt; t++) {
        if (t + 1 < nt) { loadtile((t + 1) & 1, t + 1); cpcommit(); cpwait<1>(); }
        else            { cpwait<0>(); }
        __syncthreads();
        uint32_t sa = sbase + (t & 1) * 32768;
        uint32_t sb = sa + 16384;
#pragma unroll
        for (int ks = 0; ks < 4; ks++) {
            uint32_t a[2][4];
#pragma unroll
            for (int mf = 0; mf < 2; mf++) {
                int r = wm + mf * 16 + (lane & 15);
                ldsm_x4(a[mf][0], a[mf][1], a[mf][2], a[mf][3],
                        sa + sw128(r * 128 + ks * 32 + (lane >> 4) * 16));
            }
            uint32_t bfr[8][2];
#pragma unroll
            for (int np = 0; np < 4; np++) {
                uint32_t r0, r1, r2, r3;
                int n = wn + np * 16 + (lane >> 4) * 8 + (lane & 7);
                ldsm_x4(r0, r1, r2, r3,
                        sb + sw128(n * 128 + ks * 32 + ((lane >> 3) & 1) * 16));
                bfr[np * 2][0] = r0; bfr[np * 2][1] = r1;
                bfr[np * 2 + 1][0] = r2; bfr[np * 2 + 1][1] = r3;
            }
#pragma unroll
            for (int mf = 0; mf < 2; mf++)
#pragma unroll
                for (int nf = 0; nf < 8; nf++)
                    mma16816(acc[mf][nf], a[mf], bfr[nf]);
        }
        __syncthreads();
    }

    const int g = lane >> 2, tg = lane & 3;
#pragma unroll
    for (int mf = 0; mf < 2; mf++) {
        long long r0 = m0 + wm + mf * 16 + g;
#pragma unroll
        for (int nf = 0; nf < 8; nf++) {
            long long cc = n0 + wn + nf * 8 + 2 * tg;
            float y0 = acc[mf][nf][0], y1 = acc[mf][nf][1];
            float y2 = acc[mf][nf][2], y3 = acc[mf][nf][3];
            if (EPI == 2 || EPI == 3) {
                float qb0 = qz7f(__ldg(bias + cc)), qb1 = qz7f(__ldg(bias + cc + 1));
                y0 += qb0; y1 += qb1; y2 += qb0; y3 += qb1;
            }
            if (EPI == 3) {
                y0 = fmaxf(y0, 0.0f); y1 = fmaxf(y1, 0.0f);
                y2 = fmaxf(y2, 0.0f); y3 = fmaxf(y3, 0.0f);
            }
            y0 = qz4f(y0); y1 = qz4f(y1); y2 = qz4f(y2); y3 = qz4f(y3);
            *(uint32_t*)(C + r0 * N + cc) = pack2(y0, y1);
            *(uint32_t*)(C + (r0 + 8) * N + cc) = pack2(y2, y3);
        }
    }
}

// ---------------------------------------------------------------------------
// Fused attention over combined qkv buffer (row stride 3072):
//   q cols [0,1024), k cols [1024,2048), v cols [2048,3072), head h at +h*64.
// Softmax with fixed m=0 (scores are qz4-clamped to [-8,7.94] -> exp safe).
//   pass1: l = sum exp(qz4(0.125*qk));  pass2: p = qz7(exp(s)/l), PV mma.
// ---------------------------------------------------------------------------
__global__ void __launch_bounds__(256)
attn_fused(const bf16* __restrict__ qkv, bf16* __restrict__ zq)
{
    __shared__ __align__(128) char smem_raw[49152];
    const int tid = threadIdx.x, warp = tid >> 5, lane = tid & 31;
    const int bh = blockIdx.y;
    const int b = bh >> 4, h = bh & 15;
    const long long qrow0 = (long long)b * 1024 + (long long)blockIdx.x * 128;

    const bf16* Qp = qkv + qrow0 * 3072 + h * 64;
    const bf16* Kp = qkv + (long long)b * 1024 * 3072 + 1024 + h * 64;
    const bf16* Vp = Kp + 1024;

    const uint32_t sbase = (uint32_t)__cvta_generic_to_shared(smem_raw);
    const uint32_t sQ = sbase;
    const uint32_t sS = sbase + 16384;
    const int wm = warp * 16;

    // load Q tile [128][64]
#pragma unroll
    for (int v = 0; v < 4; v++) {
        int idx = tid + v * 256;
        int r = idx >> 3, c = idx & 7;
        cpasync16(sQ + sw128(r * 128 + c * 16), Qp + (long long)r * 3072 + c * 8);
    }

    auto loadK128 = [&](int s, int c) {
        uint32_t basea = sS + s * 16384;
#pragma unroll
        for (int v = 0; v < 4; v++) {
            int idx = tid + v * 256;
            int r = idx >> 3, cd = idx & 7;
            cpasync16(basea + sw128(r * 128 + cd * 16),
                      Kp + (long long)(c * 128 + r) * 3072 + cd * 8);
        }
    };

    loadK128(0, 0); cpcommit();

    float l[2] = {0.0f, 0.0f};

    // ---------------- pass 1: row sums (m = 0) ----------------
    for (int c = 0; c < 8; c++) {
        if (c + 1 < 8) { loadK128((c + 1) & 1, c + 1); cpcommit(); cpwait<1>(); }
        else           { cpwait<0>(); }
        __syncthreads();
        uint32_t sk = sS + (c & 1) * 16384;

        float acc[16][4];
#pragma unroll
        for (int i = 0; i < 16; i++)
#pragma unroll
            for (int p = 0; p < 4; p++) acc[i][p] = 0.0f;

#pragma unroll
        for (int ks = 0; ks < 4; ks++) {
            uint32_t a[4];
            int ar = wm + (lane & 15);
            ldsm_x4(a[0], a[1], a[2], a[3],
                    sQ + sw128(ar * 128 + ks * 32 + (lane >> 4) * 16));
            uint32_t bfr[16][2];
#pragma unroll
            for (int np = 0; np < 8; np++) {
                uint32_t r0, r1, r2, r3;
                int n = np * 16 + (lane >> 4) * 8 + (lane & 7);
                ldsm_x4(r0, r1, r2, r3,
                        sk + sw128(n * 128 + ks * 32 + ((lane >> 3) & 1) * 16));
                bfr[np * 2][0] = r0; bfr[np * 2][1] = r1;
                bfr[np * 2 + 1][0] = r2; bfr[np * 2 + 1][1] = r3;
            }
#pragma unroll
            for (int nf = 0; nf < 16; nf++)
                mma16816(acc[nf], a, bfr[nf]);
        }

        float s0 = 0.0f, s1 = 0.0f;
#pragma unroll
        for (int nf = 0; nf < 16; nf++) {
            s0 += expf(qz4f(acc[nf][0] * 0.125f)) + expf(qz4f(acc[nf][1] * 0.125f));
            s1 += expf(qz4f(acc[nf][2] * 0.125f)) + expf(qz4f(acc[nf][3] * 0.125f));
        }
        s0 += __shfl_xor_sync(0xffffffffu, s0, 1);
        s0 += __shfl_xor_sync(0xffffffffu, s0, 2);
        s1 += __shfl_xor_sync(0xffffffffu, s1, 1);
        s1 += __shfl_xor_sync(0xffffffffu, s1, 2);
        l[0] += s0;
        l[1] += s1;
        __syncthreads();
    }

    const float linv0 = 1.0f / l[0], linv1 = 1.0f / l[1];

    // ---------------- pass 2: probs + PV ----------------
    auto loadKV64 = [&](int s, int c) {
        uint32_t basea = sS + s * 16384;
#pragma unroll
        for (int v = 0; v < 2; v++) {
            int idx = tid + v * 256;
            int r = idx >> 3, cd = idx & 7;
            uint32_t off = sw128(r * 128 + cd * 16);
            cpasync16(basea + off, Kp + (long long)(c * 64 + r) * 3072 + cd * 8);
            cpasync16(basea + 8192 + off, Vp + (long long)(c * 64 + r) * 3072 + cd * 8);
        }
    };

    float zacc[8][4];
#pragma unroll
    for (int j = 0; j < 8; j++)
#pragma unroll
        for (int p = 0; p < 4; p++) zacc[j][p] = 0.0f;

    loadKV64(0, 0); cpcommit();

    for (int c = 0; c < 16; c++) {
        if (c + 1 < 16) { loadKV64((c + 1) & 1, c + 1); cpcommit(); cpwait<1>(); }
        else            { cpwait<0>(); }
        __syncthreads();
        uint32_t sk = sS + (c & 1) * 16384;
        uint32_t sv = sk + 8192;

        float acc[8][4];
#pragma unroll
        for (int i = 0; i < 8; i++)
#pragma unroll
            for (int p = 0; p < 4; p++) acc[i][p] = 0.0f;

#pragma unroll
        for (int ks = 0; ks < 4; ks++) {
            uint32_t a[4];
            int ar = wm + (lane & 15);
            ldsm_x4(a[0], a[1], a[2], a[3],
                    sQ + sw128(ar * 128 + ks * 32 + (lane >> 4) * 16));
            uint32_t bfr[8][2];
#pragma unroll
            for (int np = 0; np < 4; np++) {
                uint32_t r0, r1, r2, r3;
                int n = np * 16 + (lane >> 4) * 8 + (lane & 7);
                ldsm_x4(r0, r1, r2, r3,
                        sk + sw128(n * 128 + ks * 32 + ((lane >> 3) & 1) * 16));
                bfr[np * 2][0] = r0; bfr[np * 2][1] = r1;
                bfr[np * 2 + 1][0] = r2; bfr[np * 2 + 1][1] = r3;
            }
#pragma unroll
            for (int nf = 0; nf < 8; nf++)
                mma16816(acc[nf], a, bfr[nf]);
        }

        uint32_t afr[4][4];
#pragma unroll
        for (int kk = 0; kk < 4; kk++) {
            float p00 = qz7f(expf(qz4f(acc[2 * kk][0] * 0.125f)) * linv0);
            float p01 = qz7f(expf(qz4f(acc[2 * kk][1] * 0.125f)) * linv0);
            float p02 = qz7f(expf(qz4f(acc[2 * kk][2] * 0.125f)) * linv1);
            float p03 = qz7f(expf(qz4f(acc[2 * kk][3] * 0.125f)) * linv1);
            float p10 = qz7f(expf(qz4f(acc[2 * kk + 1][0] * 0.125f)) * linv0);
            float p11 = qz7f(expf(qz4f(acc[2 * kk + 1][1] * 0.125f)) * linv0);
            float p12 = qz7f(expf(qz4f(acc[2 * kk + 1][2] * 0.125f)) * linv1);
            float p13 = qz7f(expf(qz4f(acc[2 * kk + 1][3] * 0.125f)) * linv1);
            afr[kk][0] = pack2(p00, p01);
            afr[kk][1] = pack2(p02, p03);
            afr[kk][2] = pack2(p10, p11);
            afr[kk][3] = pack2(p12, p13);
        }

#pragma unroll
        for (int kk = 0; kk < 4; kk++) {
            uint32_t vfr[8][2];
#pragma unroll
            for (int np = 0; np < 4; np++) {
                uint32_t r0, r1, r2, r3;
                int r = kk * 16 + (lane & 15);
                int n = np * 16 + (lane >> 4) * 8;
                ldsm_x4_t(r0, r1, r2, r3, sv + sw128(r * 128 + n * 2));
                vfr[np * 2][0] = r0; vfr[np * 2][1] = r1;
                vfr[np * 2 + 1][0] = r2; vfr[np * 2 + 1][1] = r3;
            }
#pragma unroll
            for (int nf = 0; nf < 8; nf++)
                mma16816(zacc[nf], afr[kk], vfr[nf]);
        }
        __syncthreads();
    }

    const int g = lane >> 2, tg = lane & 3;
    const long long r0 = qrow0 + wm + g;
#pragma unroll
    for (int nf = 0; nf < 8; nf++) {
        long long cc = (long long)h * 64 + nf * 8 + 2 * tg;
        *(uint32_t*)(zq + r0 * 1024 + cc) = pack2(qz4f(zacc[nf][0]), qz4f(zacc[nf][1]));
        *(uint32_t*)(zq + (r0 + 8) * 1024 + cc) = pack2(qz4f(zacc[nf][2]), qz4f(zacc[nf][3]));
    }
}

// ---------------------------------------------------------------------------
// Elementwise kernels
// ---------------------------------------------------------------------------
// All 5 weight tensors quantized in one launch. Block ranges (1024 elems/blk):
//  [0,1024) q_w -> wqkv rows 0-1023 ; [1024,3072) kv_w -> wqkv+1M
//  [3072,4096) proj_w ; [4096,8192) fc1_w ; [8192,12288) fc2_w
__global__ void __launch_bounds__(256) quantw_all_kernel(
    const float* __restrict__ qw, const float* __restrict__ kvw,
    const float* __restrict__ pjw, const float* __restrict__ f1w,
    const float* __restrict__ f2w,
    bf16* __restrict__ wqkv, bf16* __restrict__ wpj,
    bf16* __restrict__ wf1, bf16* __restrict__ wf2)
{
    int blk = blockIdx.x;
    const float* src; bf16* dst;
    if (blk < 1024)      { src = qw;  dst = wqkv; }
    else if (blk < 3072) { src = kvw; dst = wqkv + 1024L * 1024; blk -= 1024; }
    else if (blk < 4096) { src = pjw; dst = wpj; blk -= 3072; }
    else if (blk < 8192) { src = f1w; dst = wf1; blk -= 4096; }
    else                 { src = f2w; dst = wf2; blk -= 8192; }
    long long i = (long long)blk * 256 + threadIdx.x;
    float4 v = reinterpret_cast<const float4*>(src)[i];
    uint2 o;
    o.x = pack2(qz7f(v.x), qz7f(v.y));
    o.y = pack2(qz7f(v.z), qz7f(v.w));
    reinterpret_cast<uint2*>(dst)[i] = o;
}

__global__ void __launch_bounds__(256) affine_f32_kernel(
    const float* __restrict__ X, const float* __restrict__ w,
    const float* __restrict__ b, bf16* __restrict__ O)
{
    long long i = (long long)blockIdx.x * 256 + threadIdx.x;
    const float qw = qz4f(w[0]);
    const float qb = qz4f(b[0]);
    float4 v = reinterpret_cast<const float4*>(X)[i];
    uint2 o;
    o.x = pack2(qz4f(qz4f(qz4f(v.x) * qw) + qb), qz4f(qz4f(qz4f(v.y) * qw) + qb));
    o.y = pack2(qz4f(qz4f(qz4f(v.z) * qw) + qb), qz4f(qz4f(qz4f(v.w) * qw) + qb));
    reinterpret_cast<uint2*>(O)[i] = o;
}

// fused: x1 = qz4(x)+pj (bf16 exact), hq = qz4(affine(x1, aff2))
__global__ void __launch_bounds__(256) add1_aff2_kernel(
    const float* __restrict__ X, const bf16* __restrict__ P,
    const float* __restrict__ w, const float* __restrict__ b,
    bf16* __restrict__ X1, bf16* __restrict__ H)
{
    long long i = (long long)blockIdx.x * 256 + threadIdx.x;
    const float qw = qz4f(w[0]);
    const float qb = qz4f(b[0]);
    float4 x = reinterpret_cast<const float4*>(X)[i];
    uint2 p = reinterpret_cast<const uint2*>(P)[i];
    float p0, p1, p2, p3;
    unpack2(p.x, p0, p1); unpack2(p.y, p2, p3);
    float x10 = qz4f(x.x) + p0, x11 = qz4f(x.y) + p1;
    float x12 = qz4f(x.z) + p2, x13 = qz4f(x.w) + p3;
    uint2 ox;
    ox.x = pack2(x10, x11); ox.y = pack2(x12, x13);
    reinterpret_cast<uint2*>(X1)[i] = ox;
    uint2 oh;
    oh.x = pack2(qz4f(qz4f(qz4f(x10) * qw) + qb), qz4f(qz4f(qz4f(x11) * qw) + qb));
    oh.y = pack2(qz4f(qz4f(qz4f(x12) * qw) + qb), qz4f(qz4f(qz4f(x13) * qw) + qb));
    reinterpret_cast<uint2*>(H)[i] = oh;
}

__global__ void __launch_bounds__(256) add2_kernel(
    const bf16* __restrict__ X1, const bf16* __restrict__ F, float* __restrict__ O)
{
    long long i = (long long)blockIdx.x * 256 + threadIdx.x;
    uint2 a = reinterpret_cast<const uint2*>(X1)[i];
    uint2 f = reinterpret_cast<const uint2*>(F)[i];
    float a0, a1, a2, a3, f0, f1, f2v, f3;
    unpack2(a.x, a0, a1); unpack2(a.y, a2, a3);
    unpack2(f.x, f0, f1); unpack2(f.y, f2v, f3);
    float4 o;
    o.x = qz4f(a0) + f0; o.y = qz4f(a1) + f1;
    o.z = qz4f(a2) + f2v; o.w = qz4f(a3) + f3;
    reinterpret_cast<float4*>(O)[i] = o;
}

// ---------------------------------------------------------------------------
// Launcher
// ---------------------------------------------------------------------------
#define GEMM_SMEM 65536

extern "C" void kernel_launch(void* const* d_in, const int* in_sizes, int n_in,
                              void* d_out, int out_size)
{
    const float* x      = (const float*)d_in[0];
    const float* q_w    = (const float*)d_in[1];
    const float* kv_w   = (const float*)d_in[2];
    const float* proj_w = (const float*)d_in[3];
    const float* proj_b = (const float*)d_in[4];
    const float* fc1_w  = (const float*)d_in[5];
    const float* fc1_b  = (const float*)d_in[6];
    const float* fc2_w  = (const float*)d_in[7];
    const float* fc2_b  = (const float*)d_in[8];
    const float* aff1_w = (const float*)d_in[9];
    const float* aff1_b = (const float*)d_in[10];
    const float* aff2_w = (const float*)d_in[11];
    const float* aff2_b = (const float*)d_in[12];
    float* out = (float*)d_out;

    bf16 *hq, *qkv, *zq, *pj, *x1, *mid, *f2, *wqkv, *wpj, *wf1, *wf2;
    cudaGetSymbolAddress((void**)&hq,   g_hq);
    cudaGetSymbolAddress((void**)&qkv,  g_qkv);
    cudaGetSymbolAddress((void**)&zq,   g_zq);
    cudaGetSymbolAddress((void**)&pj,   g_pj);
    cudaGetSymbolAddress((void**)&x1,   g_x1);
    cudaGetSymbolAddress((void**)&mid,  g_mid);
    cudaGetSymbolAddress((void**)&f2,   g_f2);
    cudaGetSymbolAddress((void**)&wqkv, g_wqkv);
    cudaGetSymbolAddress((void**)&wpj,  g_wpj);
    cudaGetSymbolAddress((void**)&wf1,  g_wf1);
    cudaGetSymbolAddress((void**)&wf2,  g_wf2);

    static bool attr_done = false;
    if (!attr_done) {
        cudaFuncSetAttribute(gemm_pipe<0>, cudaFuncAttributeMaxDynamicSharedMemorySize, GEMM_SMEM);
        cudaFuncSetAttribute(gemm_pipe<2>, cudaFuncAttributeMaxDynamicSharedMemorySize, GEMM_SMEM);
        cudaFuncSetAttribute(gemm_pipe<3>, cudaFuncAttributeMaxDynamicSharedMemorySize, GEMM_SMEM);
        attr_done = true;
    }

    // 0: hq = qz4(affine(x, aff1))
    affine_f32_kernel<<<4096, 256>>>(x, aff1_w, aff1_b, hq);
    // 1: quantize all weights (q|kv combined into wqkv)
    quantw_all_kernel<<<12288, 256>>>(q_w, kv_w, proj_w, fc1_w, fc2_w,
                                      wqkv, wpj, wf1, wf2);
    // 2: qkv = qz4(hq @ wqkv^T)  [N=3072, one launch]
    gemm_pipe<0><<<dim3(24, 32), 256, GEMM_SMEM>>>(hq, wqkv, nullptr, qkv, 3072, 1024);
    // 3: fused attention (combined qkv in, bf16 zq out)
    attn_fused<<<dim3(8, 64), 256>>>(qkv, zq);
    // 4: pj = qz4(zq @ wpj^T + qz7(proj_b))
    gemm_pipe<2><<<dim3(8, 32), 256, GEMM_SMEM>>>(zq, wpj, proj_b, pj, 1024, 1024);
    // 5: x1 = qz4(x)+pj ; hq = qz4(affine(x1, aff2))   [fused]
    add1_aff2_kernel<<<4096, 256>>>(x, pj, aff2_w, aff2_b, x1, hq);
    // 6: mid = qz4(relu(hq @ wf1^T + qz7(fc1_b)))
    gemm_pipe<3><<<dim3(32, 32), 256, GEMM_SMEM>>>(hq, wf1, fc1_b, mid, 4096, 1024);
    // 7: f2 = qz4(mid @ wf2^T + qz7(fc2_b))
    gemm_pipe<2><<<dim3(8, 32), 256, GEMM_SMEM>>>(mid, wf2, fc2_b, f2, 1024, 4096);
    // 8: out = qz4(x1) + f2
    add2_kernel<<<4096, 256>>>(x1, f2, out);
}